// round 15
// baseline (speedup 1.0000x reference)
#include <cuda_runtime.h>
#include <cuda_fp16.h>
#include <cstdint>

// ---------------- problem dims ----------------
#define CIN   128
#define HIN   224
#define WIN   224
#define COUT  256
#define HO    222
#define WO    222
#define NPIX  (HO * WO)       // 49284
#define KDIM  (CIN * 9)       // 1152

// ---------------- tiling ----------------
#define BM   128
#define BN   256
#define BK   64               // fp32 K per smem stage = 4 mma K-steps of 16
#define KSTAGES (KDIM / BK)   // 18
#define NTH  256              // 8 warps: 2 (m) x 4 (n), warp tile 64x64

// ---------------- smem layout ----------------
#define A_TILE_B (128 * 128)
#define B_TILE_B (256 * 128)
#define OFF_AHI  0
#define OFF_ALO  (A_TILE_B)
#define OFF_BHI  (2 * A_TILE_B)
#define BUF_B    (2 * A_TILE_B + B_TILE_B)      // 65536
#define OFF_KOFF (2 * BUF_B)                    // 131072
#define SMEM_TOTAL (OFF_KOFF + KDIM * 4)        // 135680

// ---------------- persistent pre-split weights ----------------
__device__ __align__(16) __half g_Whi[COUT * KDIM];
__device__ __align__(16) __half g_Wlo[COUT * KDIM];

__device__ __forceinline__ uint32_t smem_u32(const void* p) {
    uint32_t a;
    asm("{ .reg .u64 t; cvta.to.shared.u64 t, %1; cvt.u32.u64 %0, t; }" : "=r"(a) : "l"(p));
    return a;
}

__device__ __forceinline__ void ldsm_x4(uint32_t* r, uint32_t addr) {
    asm volatile("ldmatrix.sync.aligned.m8n8.x4.shared.b16 {%0,%1,%2,%3}, [%4];"
                 : "=r"(r[0]), "=r"(r[1]), "=r"(r[2]), "=r"(r[3]) : "r"(addr));
}

__device__ __forceinline__ void mma_f16(float* d, const uint32_t* a, const uint32_t* b) {
    asm volatile(
        "mma.sync.aligned.m16n8k16.row.col.f32.f16.f16.f32 "
        "{%0,%1,%2,%3}, {%4,%5,%6,%7}, {%8,%9}, {%0,%1,%2,%3};"
        : "+f"(d[0]), "+f"(d[1]), "+f"(d[2]), "+f"(d[3])
        : "r"(a[0]), "r"(a[1]), "r"(a[2]), "r"(a[3]), "r"(b[0]), "r"(b[1]));
}

__device__ __forceinline__ void cpasync16(uint32_t dst, const void* src) {
    asm volatile("cp.async.cg.shared.global [%0], [%1], 16;" :: "r"(dst), "l"(src) : "memory");
}

// round 8 consecutive-k fp32 -> one fp16 chunk (B)
__device__ __forceinline__ uint4 pack8(const float* f) {
    uint32_t hb[4];
    #pragma unroll
    for (int q = 0; q < 4; q++) {
        __half2 hp = __floats2half2_rn(f[2*q], f[2*q+1]);
        hb[q] = *reinterpret_cast<uint32_t*>(&hp);
    }
    return make_uint4(hb[0], hb[1], hb[2], hb[3]);
}

// ================= pre-split kernel: W fp32 -> Whi/Wlo fp16 =================
__global__ void presplit_kernel(const float* __restrict__ Wt)
{
    const int i = blockIdx.x * blockDim.x + threadIdx.x;     // float4 index
    if (i >= COUT * KDIM / 4) return;
    float4 v = reinterpret_cast<const float4*>(Wt)[i];
    __half2 h0 = __floats2half2_rn(v.x, v.y);
    __half2 h1 = __floats2half2_rn(v.z, v.w);
    float2 f0 = __half22float2(h0), f1 = __half22float2(h1);
    __half2 l0 = __floats2half2_rn(v.x - f0.x, v.y - f0.y);
    __half2 l1 = __floats2half2_rn(v.z - f1.x, v.w - f1.y);
    __half2* hi = reinterpret_cast<__half2*>(g_Whi);
    __half2* lo = reinterpret_cast<__half2*>(g_Wlo);
    hi[2*i] = h0; hi[2*i+1] = h1;
    lo[2*i] = l0; lo[2*i+1] = l1;
}

// ================= main kernel =================
__global__ __launch_bounds__(NTH, 1)
void conv_mma3_kernel(const float* __restrict__ X,
                      float* __restrict__ O)
{
    extern __shared__ __align__(1024) char smem[];
    const int tid  = threadIdx.x;
    const int wid  = tid >> 5;
    const int lane = tid & 31;
    const uint32_t sb = smem_u32(smem);

    const int n0 = blockIdx.x * BN;
    const int m0 = blockIdx.y * BM;

    // ---- im2col offset table ----
    int* koff_w = (int*)(smem + OFF_KOFF);
    for (int i = tid; i < KDIM; i += NTH) {
        int c  = i / 9;
        int rs = i - 9 * c;
        int r  = rs / 3;
        koff_w[i] = c * (HIN * WIN) + r * WIN + (rs - 3 * r);
    }
    __syncthreads();
    const int* koff = (const int*)(smem + OFF_KOFF);

    // ---- B load mapping: one pixel row per thread ----
    int np = n0 + tid;
    if (np >= NPIX) np = NPIX - 1;
    const float* Xp = X + np + 2 * (np / WO);
    const uint32_t brow = (uint32_t)(tid * 128);
    const uint32_t bswz = (uint32_t)(tid & 7);

    // ---- A cp.async mapping: thread -> one 128B row of AHI or ALO ----
    const int a_row = tid & 127;
    const int a_hl  = tid >> 7;                       // 0 = hi, 1 = lo
    const __half* a_src = (a_hl ? g_Wlo : g_Whi) + (size_t)(m0 + a_row) * KDIM;
    const uint32_t a_dst = (uint32_t)((a_hl ? OFF_ALO : OFF_AHI) + a_row * 128);
    const uint32_t a_swz = (uint32_t)(a_row & 7);

    // ---- warp tile mapping: 64 (m) x 64 (n) ----
    const int wm = wid & 1;
    const int wn = wid >> 1;

    const uint32_t aswz   = (uint32_t)(lane & 7);
    const int      g      = lane >> 3;
    const uint32_t a_coff = (uint32_t)(g >> 1);
    const uint32_t b_coff = (uint32_t)(g & 1);
    uint32_t arowb[4], bnb[4];
    #pragma unroll
    for (int mf = 0; mf < 4; mf++)
        arowb[mf] = (uint32_t)((wm * 64 + mf * 16 + ((g & 1) << 3) + (lane & 7)) << 7);
    #pragma unroll
    for (int nf2 = 0; nf2 < 4; nf2++)
        bnb[nf2] = (uint32_t)((wn * 64 + nf2 * 16 + ((g >> 1) << 3) + (lane & 7)) << 7);

    float acc[4][8][4];
    #pragma unroll
    for (int i = 0; i < 4; i++)
        #pragma unroll
        for (int j = 0; j < 8; j++)
            #pragma unroll
            for (int q = 0; q < 4; q++) acc[i][j][q] = 0.0f;

    // ---- prologue: A(0) via cp.async, B(0) via gather+STS into buffer 0 ----
    {
        #pragma unroll
        for (int c = 0; c < 8; c++)
            cpasync16(sb + a_dst + (((uint32_t)c ^ a_swz) << 4), a_src + c * 8);
        asm volatile("cp.async.commit_group;" ::: "memory");

        char* bufp = smem;
        #pragma unroll
        for (int c = 0; c < 8; c++) {
            float fb[8];
            #pragma unroll
            for (int jj = 0; jj < 8; jj++) fb[jj] = Xp[koff[c * 8 + jj]];
            const uint32_t off = brow + ((((uint32_t)c) ^ bswz) << 4);
            *(uint4*)(bufp + OFF_BHI + off) = pack8(fb);
        }
    }

    // ---- main loop ----
    for (int s = 0; s < KSTAGES; s++) {
        const int buf = s & 1;
        const bool more = (s + 1 < KSTAGES);
        const int kn = (s + 1) * BK;

        // stage-s operands ready: this thread's A copies done + everyone's STS/copies visible
        asm volatile("cp.async.wait_group 0;" ::: "memory");
        __syncthreads();

        // issue A(s+1) into the other buffer — covered by compute(s)
        if (more) {
            const uint32_t dst = sb + (buf ^ 1) * BUF_B + a_dst;
            const __half* src = a_src + kn;
            #pragma unroll
            for (int c = 0; c < 8; c++)
                cpasync16(dst + (((uint32_t)c ^ a_swz) << 4), src + c * 8);
            asm volatile("cp.async.commit_group;" ::: "memory");
        }

        // prefetch first half of next B stage into registers
        float bpf[32];
        if (more) {
            #pragma unroll
            for (int j = 0; j < 32; j++) bpf[j] = Xp[koff[kn + j]];
        }

        // ---- compute on current buffer ----
        {
            const uint32_t ahiB = sb + buf * BUF_B + OFF_AHI;
            const uint32_t aloB = sb + buf * BUF_B + OFF_ALO;
            const uint32_t bhiB = sb + buf * BUF_B + OFF_BHI;

            #pragma unroll
            for (int ks = 0; ks < 4; ks++) {
                const uint32_t kc = (uint32_t)(2 * ks);
                const uint32_t aoff = ((kc + a_coff) ^ aswz) << 4;
                const uint32_t boff = ((kc + b_coff) ^ aswz) << 4;

                uint32_t ah[4][4], al[4][4], bh[4][4];
                #pragma unroll
                for (int mf = 0; mf < 4; mf++) {
                    ldsm_x4(ah[mf], ahiB + arowb[mf] + aoff);
                    ldsm_x4(al[mf], aloB + arowb[mf] + aoff);
                }
                #pragma unroll
                for (int nf2 = 0; nf2 < 4; nf2++)
                    ldsm_x4(bh[nf2], bhiB + bnb[nf2] + boff);

                #pragma unroll
                for (int mf = 0; mf < 4; mf++)
                    #pragma unroll
                    for (int nf = 0; nf < 8; nf++) {
                        const uint32_t* bp = &bh[nf >> 1][(nf & 1) * 2];
                        mma_f16(acc[mf][nf], ah[mf], bp);   // Ah * Bh
                        mma_f16(acc[mf][nf], al[mf], bp);   // Al * Bh
                    }
            }
        }

        // ---- B fill for next stage into other buffer ----
        if (more) {
            char* bufp = smem + (buf ^ 1) * BUF_B;
            #pragma unroll
            for (int c = 0; c < 4; c++) {
                const uint32_t off = brow + ((((uint32_t)c) ^ bswz) << 4);
                *(uint4*)(bufp + OFF_BHI + off) = pack8(&bpf[c * 8]);
            }
            #pragma unroll
            for (int c = 4; c < 8; c++) {
                float fb[8];
                #pragma unroll
                for (int jj = 0; jj < 8; jj++) fb[jj] = Xp[koff[kn + c * 8 + jj]];
                const uint32_t off = brow + ((((uint32_t)c) ^ bswz) << 4);
                *(uint4*)(bufp + OFF_BHI + off) = pack8(fb);
            }
        }
    }

    // ---- epilogue ----
    const bool full = (n0 + BN <= NPIX);
    #pragma unroll
    for (int mf = 0; mf < 4; mf++) {
        const int r0 = m0 + wm * 64 + mf * 16 + (lane >> 2);
        #pragma unroll
        for (int nf = 0; nf < 8; nf++) {
            const int c = n0 + wn * 64 + nf * 8 + (lane & 3) * 2;
            float* p0 = O + (size_t)r0 * NPIX + c;
            float* p1 = p0 + 8 * NPIX;
            if (full) {
                *(float2*)p0 = make_float2(acc[mf][nf][0], acc[mf][nf][1]);
                *(float2*)p1 = make_float2(acc[mf][nf][2], acc[mf][nf][3]);
            } else {
                if (c < NPIX)     { p0[0] = acc[mf][nf][0]; p1[0] = acc[mf][nf][2]; }
                if (c + 1 < NPIX) { p0[1] = acc[mf][nf][1]; p1[1] = acc[mf][nf][3]; }
            }
        }
    }
}

extern "C" void kernel_launch(void* const* d_in, const int* in_sizes, int n_in,
                              void* d_out, int out_size)
{
    const float* X  = (const float*)d_in[0];   // (128, 224, 224) fp32
    const float* Wt = (const float*)d_in[1];   // (256, 128, 3, 3) fp32
    float* O        = (float*)d_out;           // (256, 222, 222) fp32

    // 1) split weights into fp16 hi/lo (persistent device buffers)
    presplit_kernel<<<(COUT * KDIM / 4 + 255) / 256, 256>>>(Wt);

    // 2) main implicit-GEMM conv
    cudaFuncSetAttribute(conv_mma3_kernel,
                         cudaFuncAttributeMaxDynamicSharedMemorySize, SMEM_TOTAL);
    dim3 grid((NPIX + BN - 1) / BN, COUT / BM);   // 193 x 2 = 386 CTAs
    conv_mma3_kernel<<<grid, NTH, SMEM_TOTAL>>>(X, O);
}